// round 4
// baseline (speedup 1.0000x reference)
#include <cuda_runtime.h>
#include <cuda_bf16.h>

// Sizes (fixed): B=64, T=1024, D=512, H=256, 4H=1024, two directions.

// ---------------------------------------------------------------------------
// Scratch (device globals -- no allocation allowed)
// ---------------------------------------------------------------------------
__device__ float G_buf [(size_t)65536 * 2048];        // [m = b*1024 + t][j(0..2047)]
__device__ float Gt_buf[(size_t)1024 * 2048 * 64];    // [t][j][b]
__device__ float h_glob[2][2][16384];                 // [phase][dir][k*64 + b]
__device__ volatile unsigned g_flag[2][64];           // per-direction per-CTA step flags

// ---------------------------------------------------------------------------
// f32x2 packed-math helpers
// ---------------------------------------------------------------------------
static __device__ __forceinline__ unsigned long long pk2(float x, float y) {
    unsigned long long r;
    asm("mov.b64 %0, {%1, %2};" : "=l"(r) : "f"(x), "f"(y));
    return r;
}
static __device__ __forceinline__ unsigned long long fma2(
    unsigned long long a, unsigned long long b, unsigned long long c) {
    unsigned long long d;
    asm("fma.rn.f32x2 %0, %1, %2, %3;" : "=l"(d) : "l"(a), "l"(b), "l"(c));
    return d;
}
static __device__ __forceinline__ float2 upk(unsigned long long v) {
    float2 r;
    asm("mov.b64 {%0, %1}, %2;" : "=f"(r.x), "=f"(r.y) : "l"(v));
    return r;
}

static __device__ __forceinline__ float sigm_f(float x) {
    return __frcp_rn(1.f + __expf(-x));
}
static __device__ __forceinline__ float tanh_f(float x) {
    x = fminf(fmaxf(x, -15.f), 15.f);
    float e = __expf(2.f * x);
    return (e - 1.f) / (e + 1.f);
}

// ---------------------------------------------------------------------------
// Reset: zero h state (both phases) and barrier flags. Runs every launch.
// ---------------------------------------------------------------------------
__global__ void reset_k() {
    unsigned i = blockIdx.x * 256u + threadIdx.x;
    float* h = &h_glob[0][0][0];
    if (i < 65536u) h[i] = 0.f;
    if (i < 128u) ((volatile unsigned*)&g_flag[0][0])[i] = 0u;
}

// ---------------------------------------------------------------------------
// Phase 1: G[m][j] = x[m,:] . Wih[j,:] + bih[j] + bhh[j]
// 128x128x8 tiles, 256 threads, 8x8 per-thread, f32x2 packed FMA.
// ---------------------------------------------------------------------------
__global__ void __launch_bounds__(256) gemm_in(
    const float* __restrict__ A,
    const float* __restrict__ Wf, const float* __restrict__ Wb,
    const float* __restrict__ bif, const float* __restrict__ bhf,
    const float* __restrict__ bib, const float* __restrict__ bhb)
{
    __shared__ float As[8][132];
    __shared__ float Bs[8][132];

    const int bn = blockIdx.x;          // 0..15
    const int bm = blockIdx.y;          // 0..511
    const bool fwd = (bn < 8);
    const float* Bm = fwd ? Wf : Wb;
    const int nloc = (bn & 7) * 128;

    const int tid = threadIdx.x;
    const int lr  = tid >> 1;
    const int lk  = (tid & 1) * 4;

    const float* Ap = A  + (size_t)(bm * 128 + lr) * 512 + lk;
    const float* Bp = Bm + (size_t)(nloc + lr) * 512 + lk;

    const int tx = tid & 15;
    const int ty = tid >> 4;

    unsigned long long acc[8][4];
#pragma unroll
    for (int i = 0; i < 8; i++)
#pragma unroll
        for (int j = 0; j < 4; j++) acc[i][j] = 0ull;

    float4 pa = *(const float4*)(Ap);
    float4 pb = *(const float4*)(Bp);

    for (int k0 = 0; k0 < 512; k0 += 8) {
        As[lk + 0][lr] = pa.x; As[lk + 1][lr] = pa.y;
        As[lk + 2][lr] = pa.z; As[lk + 3][lr] = pa.w;
        Bs[lk + 0][lr] = pb.x; Bs[lk + 1][lr] = pb.y;
        Bs[lk + 2][lr] = pb.z; Bs[lk + 3][lr] = pb.w;
        __syncthreads();

        if (k0 + 8 < 512) {
            pa = *(const float4*)(Ap + k0 + 8);
            pb = *(const float4*)(Bp + k0 + 8);
        }

#pragma unroll
        for (int kk = 0; kk < 8; kk++) {
            float4 a0 = *(const float4*)&As[kk][ty * 8];
            float4 a1 = *(const float4*)&As[kk][ty * 8 + 4];
            float4 b0 = *(const float4*)&Bs[kk][tx * 8];
            float4 b1 = *(const float4*)&Bs[kk][tx * 8 + 4];
            unsigned long long bb[4] = {
                pk2(b0.x, b0.y), pk2(b0.z, b0.w),
                pk2(b1.x, b1.y), pk2(b1.z, b1.w)
            };
            float av[8] = {a0.x, a0.y, a0.z, a0.w, a1.x, a1.y, a1.z, a1.w};
#pragma unroll
            for (int i = 0; i < 8; i++) {
                unsigned long long aa = pk2(av[i], av[i]);
#pragma unroll
                for (int j = 0; j < 4; j++)
                    acc[i][j] = fma2(aa, bb[j], acc[i][j]);
            }
        }
        __syncthreads();
    }

    const float* bi = fwd ? bif : bib;
    const float* bh = fwd ? bhf : bhb;
    float bias[8];
#pragma unroll
    for (int j = 0; j < 8; j++) {
        int nl = nloc + tx * 8 + j;
        bias[j] = bi[nl] + bh[nl];
    }
#pragma unroll
    for (int i = 0; i < 8; i++) {
        int m = bm * 128 + ty * 8 + i;
        float* dst = G_buf + (size_t)m * 2048 + bn * 128 + tx * 8;
        float2 c0 = upk(acc[i][0]), c1 = upk(acc[i][1]);
        float2 c2 = upk(acc[i][2]), c3 = upk(acc[i][3]);
        *(float4*)dst       = make_float4(c0.x + bias[0], c0.y + bias[1],
                                          c1.x + bias[2], c1.y + bias[3]);
        *(float4*)(dst + 4) = make_float4(c2.x + bias[4], c2.y + bias[5],
                                          c3.x + bias[6], c3.y + bias[7]);
    }
}

// ---------------------------------------------------------------------------
// Transpose G[b*1024+t][j] -> Gt[t][j][b]
// ---------------------------------------------------------------------------
__global__ void __launch_bounds__(256) transp() {
    __shared__ float tile[64][65];
    const int t  = blockIdx.y;
    const int j0 = blockIdx.x * 64;
    const int tid = threadIdx.x;

    const int jq = (tid & 15) * 4;
    const int bb = tid >> 4;
#pragma unroll
    for (int p = 0; p < 4; p++) {
        int bi = bb + p * 16;
        float4 v = *(const float4*)(G_buf + ((size_t)(bi * 1024 + t)) * 2048 + j0 + jq);
        tile[bi][jq + 0] = v.x; tile[bi][jq + 1] = v.y;
        tile[bi][jq + 2] = v.z; tile[bi][jq + 3] = v.w;
    }
    __syncthreads();

    const int bq = (tid & 15) * 4;
    const int jj = tid >> 4;
#pragma unroll
    for (int p = 0; p < 4; p++) {
        int j = jj + p * 16;
        float4 v = make_float4(tile[bq + 0][j], tile[bq + 1][j],
                               tile[bq + 2][j], tile[bq + 3][j]);
        *(float4*)(Gt_buf + ((size_t)t * 2048 + j0 + j) * 64 + bq) = v;
    }
}

// ---------------------------------------------------------------------------
// Phase 2: persistent recurrence. 128 CTAs (64 per direction), 256 threads.
// Identical to R3 except: HOT SPIN barrier (no __nanosleep).
// ---------------------------------------------------------------------------
__global__ void __launch_bounds__(256, 1) recur(
    const float* __restrict__ Whf, const float* __restrict__ Whb,
    float* __restrict__ out)
{
    extern __shared__ float sm[];
    float* h_s = sm;                                   // [256][64] = 16384 f
    ulonglong2* w_s = (ulonglong2*)(sm + 16384);       // [4][256]

    const int cta   = blockIdx.x;
    const int dir   = cta >> 6;
    const int slice = cta & 63;
    const int qb    = slice * 4;
    const int tid   = threadIdx.x;
    const int b     = tid & 63;
    const int qt    = tid >> 6;
    const int q     = qb + qt;

    const float* W = dir ? Whb : Whf;
    for (int idx = tid; idx < 1024; idx += 256) {
        int qq = idx >> 8;
        int k  = idx & 255;
        int qg = qb + qq;
        ulonglong2 v;
        v.x = pk2(W[(size_t)(      qg) * 256 + k], W[(size_t)(256 + qg) * 256 + k]);
        v.y = pk2(W[(size_t)(512 + qg) * 256 + k], W[(size_t)(768 + qg) * 256 + k]);
        w_s[qq * 256 + k] = v;
    }

    const ulonglong2* wrow = w_s + qt * 256;
    float c = 0.f;

    // Prefetch gate pre-activations for step 0
    int t = dir ? 1023 : 0;
    const float* gp = Gt_buf + ((size_t)t * 2048 + (size_t)dir * 1024) * 64 + b;
    float pi = __ldg(gp + (size_t)(      q) * 64);
    float pf = __ldg(gp + (size_t)(256 + q) * 64);
    float pg = __ldg(gp + (size_t)(512 + q) * 64);
    float po = __ldg(gp + (size_t)(768 + q) * 64);

    for (int step = 0; step < 1024; ++step) {
        // Stage h (64KB) from the current phase buffer; batched L2 loads.
        {
            const float4* src = (const float4*)(&h_glob[step & 1][dir][0]);
            float4* dst = (float4*)h_s;
            float4 v[16];
#pragma unroll
            for (int i = 0; i < 16; i++)
                v[i] = __ldcg(src + tid + i * 256);
#pragma unroll
            for (int i = 0; i < 16; i++)
                dst[tid + i * 256] = v[i];
        }
        __syncthreads();   // also covers w_s on the first iteration

        unsigned long long aif = pk2(pi, pf);
        unsigned long long ago = pk2(pg, po);

#pragma unroll 8
        for (int k = 0; k < 256; ++k) {
            float hv = h_s[k * 64 + b];
            ulonglong2 wv = wrow[k];
            unsigned long long hh = pk2(hv, hv);
            aif = fma2(hh, wv.x, aif);
            ago = fma2(hh, wv.y, ago);
        }

        float2 vif = upk(aif), vgo = upk(ago);
        float ig = sigm_f(vif.x);
        float fg = sigm_f(vif.y);
        float gg = tanh_f(vgo.x);
        float og = sigm_f(vgo.y);
        c = fg * c + ig * gg;
        float hn = og * tanh_f(c);

        out[((size_t)b * 1024 + t) * 512 + (size_t)dir * 256 + q] = hn;
        __stcg(&h_glob[(step + 1) & 1][dir][q * 64 + b], hn);

        if (step == 1023) break;

        // ---- grid barrier (per direction): release, signal, hot-spin, acquire
        __threadfence();
        __syncthreads();
        if (tid == 0) g_flag[dir][slice] = (unsigned)(step + 1);

        // Prefetch next step's gates while other CTAs catch up (read-only data)
        t = dir ? (1022 - step) : (step + 1);
        gp = Gt_buf + ((size_t)t * 2048 + (size_t)dir * 1024) * 64 + b;
        pi = __ldg(gp + (size_t)(      q) * 64);
        pf = __ldg(gp + (size_t)(256 + q) * 64);
        pg = __ldg(gp + (size_t)(512 + q) * 64);
        po = __ldg(gp + (size_t)(768 + q) * 64);

        if (tid < 64) {
            while (g_flag[dir][tid] <= (unsigned)step) { /* hot spin */ }
        }
        __syncthreads();
        __threadfence();
    }
}

// ---------------------------------------------------------------------------
// Launch
// ---------------------------------------------------------------------------
extern "C" void kernel_launch(void* const* d_in, const int* in_sizes, int n_in,
                              void* d_out, int out_size) {
    const float* x   = (const float*)d_in[0];
    const float* Wif = (const float*)d_in[1];
    const float* Whf = (const float*)d_in[2];
    const float* bif = (const float*)d_in[3];
    const float* bhf = (const float*)d_in[4];
    const float* Wib = (const float*)d_in[5];
    const float* Whb = (const float*)d_in[6];
    const float* bib = (const float*)d_in[7];
    const float* bhb = (const float*)d_in[8];
    float* out = (float*)d_out;

    cudaFuncSetAttribute(recur, cudaFuncAttributeMaxDynamicSharedMemorySize, 81920);

    reset_k<<<256, 256>>>();
    gemm_in<<<dim3(16, 512), 256>>>(x, Wif, Wib, bif, bhf, bib, bhb);
    transp<<<dim3(32, 1024), 256>>>();
    recur<<<128, 256, 81920>>>(Whf, Whb, out);
}

// round 5
// speedup vs baseline: 1.7484x; 1.7484x over previous
#include <cuda_runtime.h>
#include <cuda_bf16.h>

// Sizes (fixed): B=64, T=1024, D=512, H=256, 4H=1024, two directions.

// ---------------------------------------------------------------------------
// Scratch (device globals -- no allocation allowed)
// ---------------------------------------------------------------------------
__device__ float G_buf [(size_t)65536 * 2048];        // [m = b*1024 + t][j(0..2047)]
__device__ float Gt_buf[(size_t)1024 * 2048 * 64];    // [t][j][b]
__device__ float h_glob[2][2][16384];                 // [phase][dir][k*64 + b]
__device__ unsigned g_arrive[2][64][32];              // padded: one 128B line per (dir,slice)
__device__ unsigned g_epoch[2][32];                   // one 128B line per dir

// ---------------------------------------------------------------------------
// f32x2 packed-math helpers
// ---------------------------------------------------------------------------
static __device__ __forceinline__ unsigned long long pk2(float x, float y) {
    unsigned long long r;
    asm("mov.b64 %0, {%1, %2};" : "=l"(r) : "f"(x), "f"(y));
    return r;
}
static __device__ __forceinline__ unsigned long long fma2(
    unsigned long long a, unsigned long long b, unsigned long long c) {
    unsigned long long d;
    asm("fma.rn.f32x2 %0, %1, %2, %3;" : "=l"(d) : "l"(a), "l"(b), "l"(c));
    return d;
}
static __device__ __forceinline__ float2 upk(unsigned long long v) {
    float2 r;
    asm("mov.b64 {%0, %1}, %2;" : "=f"(r.x), "=f"(r.y) : "l"(v));
    return r;
}

static __device__ __forceinline__ float sigm_f(float x) {
    return __frcp_rn(1.f + __expf(-x));
}
static __device__ __forceinline__ float tanh_f(float x) {
    x = fminf(fmaxf(x, -15.f), 15.f);
    float e = __expf(2.f * x);
    return (e - 1.f) / (e + 1.f);
}

static __device__ __forceinline__ void st_rel(unsigned* p, unsigned v) {
    asm volatile("st.release.gpu.u32 [%0], %1;" :: "l"(p), "r"(v) : "memory");
}
static __device__ __forceinline__ unsigned ld_acq(const unsigned* p) {
    unsigned v;
    asm volatile("ld.acquire.gpu.u32 %0, [%1];" : "=r"(v) : "l"(p) : "memory");
    return v;
}

// ---------------------------------------------------------------------------
// Reset: zero h state (both phases) and barrier state. Runs every launch.
// ---------------------------------------------------------------------------
__global__ void reset_k() {
    unsigned i = blockIdx.x * 256u + threadIdx.x;
    float* h = &h_glob[0][0][0];
    if (i < 65536u) h[i] = 0.f;
    if (i < 4096u) (&g_arrive[0][0][0])[i] = 0u;
    if (i < 64u)   (&g_epoch[0][0])[i] = 0u;
}

// ---------------------------------------------------------------------------
// Phase 1: G[m][j] = x[m,:] . Wih[j,:] + bih[j] + bhh[j]
// 128x128x8 tiles, 256 threads, 8x8 per-thread, f32x2 packed FMA.
// ---------------------------------------------------------------------------
__global__ void __launch_bounds__(256) gemm_in(
    const float* __restrict__ A,
    const float* __restrict__ Wf, const float* __restrict__ Wb,
    const float* __restrict__ bif, const float* __restrict__ bhf,
    const float* __restrict__ bib, const float* __restrict__ bhb)
{
    __shared__ float As[8][132];
    __shared__ float Bs[8][132];

    const int bn = blockIdx.x;          // 0..15
    const int bm = blockIdx.y;          // 0..511
    const bool fwd = (bn < 8);
    const float* Bm = fwd ? Wf : Wb;
    const int nloc = (bn & 7) * 128;

    const int tid = threadIdx.x;
    const int lr  = tid >> 1;
    const int lk  = (tid & 1) * 4;

    const float* Ap = A  + (size_t)(bm * 128 + lr) * 512 + lk;
    const float* Bp = Bm + (size_t)(nloc + lr) * 512 + lk;

    const int tx = tid & 15;
    const int ty = tid >> 4;

    unsigned long long acc[8][4];
#pragma unroll
    for (int i = 0; i < 8; i++)
#pragma unroll
        for (int j = 0; j < 4; j++) acc[i][j] = 0ull;

    float4 pa = *(const float4*)(Ap);
    float4 pb = *(const float4*)(Bp);

    for (int k0 = 0; k0 < 512; k0 += 8) {
        As[lk + 0][lr] = pa.x; As[lk + 1][lr] = pa.y;
        As[lk + 2][lr] = pa.z; As[lk + 3][lr] = pa.w;
        Bs[lk + 0][lr] = pb.x; Bs[lk + 1][lr] = pb.y;
        Bs[lk + 2][lr] = pb.z; Bs[lk + 3][lr] = pb.w;
        __syncthreads();

        if (k0 + 8 < 512) {
            pa = *(const float4*)(Ap + k0 + 8);
            pb = *(const float4*)(Bp + k0 + 8);
        }

#pragma unroll
        for (int kk = 0; kk < 8; kk++) {
            float4 a0 = *(const float4*)&As[kk][ty * 8];
            float4 a1 = *(const float4*)&As[kk][ty * 8 + 4];
            float4 b0 = *(const float4*)&Bs[kk][tx * 8];
            float4 b1 = *(const float4*)&Bs[kk][tx * 8 + 4];
            unsigned long long bb[4] = {
                pk2(b0.x, b0.y), pk2(b0.z, b0.w),
                pk2(b1.x, b1.y), pk2(b1.z, b1.w)
            };
            float av[8] = {a0.x, a0.y, a0.z, a0.w, a1.x, a1.y, a1.z, a1.w};
#pragma unroll
            for (int i = 0; i < 8; i++) {
                unsigned long long aa = pk2(av[i], av[i]);
#pragma unroll
                for (int j = 0; j < 4; j++)
                    acc[i][j] = fma2(aa, bb[j], acc[i][j]);
            }
        }
        __syncthreads();
    }

    const float* bi = fwd ? bif : bib;
    const float* bh = fwd ? bhf : bhb;
    float bias[8];
#pragma unroll
    for (int j = 0; j < 8; j++) {
        int nl = nloc + tx * 8 + j;
        bias[j] = bi[nl] + bh[nl];
    }
#pragma unroll
    for (int i = 0; i < 8; i++) {
        int m = bm * 128 + ty * 8 + i;
        float* dst = G_buf + (size_t)m * 2048 + bn * 128 + tx * 8;
        float2 c0 = upk(acc[i][0]), c1 = upk(acc[i][1]);
        float2 c2 = upk(acc[i][2]), c3 = upk(acc[i][3]);
        *(float4*)dst       = make_float4(c0.x + bias[0], c0.y + bias[1],
                                          c1.x + bias[2], c1.y + bias[3]);
        *(float4*)(dst + 4) = make_float4(c2.x + bias[4], c2.y + bias[5],
                                          c3.x + bias[6], c3.y + bias[7]);
    }
}

// ---------------------------------------------------------------------------
// Transpose G[b*1024+t][j] -> Gt[t][j][b]
// ---------------------------------------------------------------------------
__global__ void __launch_bounds__(256) transp() {
    __shared__ float tile[64][65];
    const int t  = blockIdx.y;
    const int j0 = blockIdx.x * 64;
    const int tid = threadIdx.x;

    const int jq = (tid & 15) * 4;
    const int bb = tid >> 4;
#pragma unroll
    for (int p = 0; p < 4; p++) {
        int bi = bb + p * 16;
        float4 v = *(const float4*)(G_buf + ((size_t)(bi * 1024 + t)) * 2048 + j0 + jq);
        tile[bi][jq + 0] = v.x; tile[bi][jq + 1] = v.y;
        tile[bi][jq + 2] = v.z; tile[bi][jq + 3] = v.w;
    }
    __syncthreads();

    const int bq = (tid & 15) * 4;
    const int jj = tid >> 4;
#pragma unroll
    for (int p = 0; p < 4; p++) {
        int j = jj + p * 16;
        float4 v = make_float4(tile[bq + 0][j], tile[bq + 1][j],
                               tile[bq + 2][j], tile[bq + 3][j]);
        *(float4*)(Gt_buf + ((size_t)t * 2048 + j0 + j) * 64 + bq) = v;
    }
}

// ---------------------------------------------------------------------------
// Phase 2: persistent recurrence. 128 CTAs (64 per direction), 256 threads.
// Two-level low-contention barrier: padded arrive flags (one 128B line per
// CTA, single poller each in the master CTA) -> epoch broadcast (one poller
// per CTA). release/acquire semantics; one threadfence per step; out[] store
// and gate prefetch hidden under the barrier wait.
// ---------------------------------------------------------------------------
__global__ void __launch_bounds__(256, 1) recur(
    const float* __restrict__ Whf, const float* __restrict__ Whb,
    float* __restrict__ out)
{
    extern __shared__ float sm[];
    float* h_s = sm;                                   // [256][64] = 16384 f
    ulonglong2* w_s = (ulonglong2*)(sm + 16384);       // [4][256]

    const int cta   = blockIdx.x;
    const int dir   = cta >> 6;
    const int slice = cta & 63;
    const int qb    = slice * 4;
    const int tid   = threadIdx.x;
    const int b     = tid & 63;
    const int qt    = tid >> 6;
    const int q     = qb + qt;

    const float* W = dir ? Whb : Whf;
    for (int idx = tid; idx < 1024; idx += 256) {
        int qq = idx >> 8;
        int k  = idx & 255;
        int qg = qb + qq;
        ulonglong2 v;
        v.x = pk2(W[(size_t)(      qg) * 256 + k], W[(size_t)(256 + qg) * 256 + k]);
        v.y = pk2(W[(size_t)(512 + qg) * 256 + k], W[(size_t)(768 + qg) * 256 + k]);
        w_s[qq * 256 + k] = v;
    }

    const ulonglong2* wrow = w_s + qt * 256;
    float c = 0.f;

    // Prefetch gate pre-activations for step 0
    int t = dir ? 1023 : 0;
    const float* gp = Gt_buf + ((size_t)t * 2048 + (size_t)dir * 1024) * 64 + b;
    float pi = __ldg(gp + (size_t)(      q) * 64);
    float pf = __ldg(gp + (size_t)(256 + q) * 64);
    float pg = __ldg(gp + (size_t)(512 + q) * 64);
    float po = __ldg(gp + (size_t)(768 + q) * 64);

    for (int step = 0; step < 1024; ++step) {
        // Stage h (64KB) from the current phase buffer; batched L2 loads.
        {
            const float4* src = (const float4*)(&h_glob[step & 1][dir][0]);
            float4* dst = (float4*)h_s;
            float4 v[16];
#pragma unroll
            for (int i = 0; i < 16; i++)
                v[i] = __ldcg(src + tid + i * 256);
#pragma unroll
            for (int i = 0; i < 16; i++)
                dst[tid + i * 256] = v[i];
        }
        __syncthreads();   // also covers w_s on the first iteration

        unsigned long long aif = pk2(pi, pf);
        unsigned long long ago = pk2(pg, po);

#pragma unroll 8
        for (int k = 0; k < 256; ++k) {
            float hv = h_s[k * 64 + b];
            ulonglong2 wv = wrow[k];
            unsigned long long hh = pk2(hv, hv);
            aif = fma2(hh, wv.x, aif);
            ago = fma2(hh, wv.y, ago);
        }

        float2 vif = upk(aif), vgo = upk(ago);
        float ig = sigm_f(vif.x);
        float fg = sigm_f(vif.y);
        float gg = tanh_f(vgo.x);
        float og = sigm_f(vgo.y);
        c = fg * c + ig * gg;
        float hn = og * tanh_f(c);

        __stcg(&h_glob[(step + 1) & 1][dir][q * 64 + b], hn);

        if (step == 1023) {
            out[((size_t)b * 1024 + t) * 512 + (size_t)dir * 256 + q] = hn;
            break;
        }

        // ---- arrive: push h stores, signal this CTA's padded flag ----
        __threadfence();
        __syncthreads();
        if (tid == 0) st_rel(&g_arrive[dir][slice][0], (unsigned)(step + 1));

        // Hidden under the wait: output store + next step's gate prefetch
        out[((size_t)b * 1024 + t) * 512 + (size_t)dir * 256 + q] = hn;
        t = dir ? (1022 - step) : (step + 1);
        gp = Gt_buf + ((size_t)t * 2048 + (size_t)dir * 1024) * 64 + b;
        pi = __ldg(gp + (size_t)(      q) * 64);
        pf = __ldg(gp + (size_t)(256 + q) * 64);
        pg = __ldg(gp + (size_t)(512 + q) * 64);
        po = __ldg(gp + (size_t)(768 + q) * 64);

        // ---- wait: master aggregates 64 flags (1 poller per line), then
        //      publishes epoch; everyone else polls epoch with one thread ----
        if (slice == 0) {
            if (tid < 64) {
                while (ld_acq(&g_arrive[dir][tid][0]) <= (unsigned)step) {}
            }
            __syncthreads();
            if (tid == 0) st_rel(&g_epoch[dir][0], (unsigned)(step + 1));
        }
        if (tid == 0) {
            while (ld_acq(&g_epoch[dir][0]) <= (unsigned)step) {}
        }
        __syncthreads();
    }
}

// ---------------------------------------------------------------------------
// Launch
// ---------------------------------------------------------------------------
extern "C" void kernel_launch(void* const* d_in, const int* in_sizes, int n_in,
                              void* d_out, int out_size) {
    const float* x   = (const float*)d_in[0];
    const float* Wif = (const float*)d_in[1];
    const float* Whf = (const float*)d_in[2];
    const float* bif = (const float*)d_in[3];
    const float* bhf = (const float*)d_in[4];
    const float* Wib = (const float*)d_in[5];
    const float* Whb = (const float*)d_in[6];
    const float* bib = (const float*)d_in[7];
    const float* bhb = (const float*)d_in[8];
    float* out = (float*)d_out;

    cudaFuncSetAttribute(recur, cudaFuncAttributeMaxDynamicSharedMemorySize, 81920);

    reset_k<<<256, 256>>>();
    gemm_in<<<dim3(16, 512), 256>>>(x, Wif, Wib, bif, bhf, bib, bhb);
    transp<<<dim3(32, 1024), 256>>>();
    recur<<<128, 256, 81920>>>(Whf, Whb, out);
}

// round 6
// speedup vs baseline: 1.9457x; 1.1128x over previous
#include <cuda_runtime.h>
#include <cuda_bf16.h>

// Sizes (fixed): B=64, T=1024, D=512, H=256, 4H=1024, two directions.

// ---------------------------------------------------------------------------
// Scratch (device globals -- no allocation allowed)
// ---------------------------------------------------------------------------
__device__ float G_buf [(size_t)65536 * 2048];        // [m = b*1024 + t][j(0..2047)]
__device__ float Gt_buf[(size_t)1024 * 2048 * 64];    // [t][j][b]
__device__ float h_glob[2][2][16384];                 // [phase][dir][k*64 + b]
__device__ unsigned g_arrive[2][64][32];              // padded: one 128B line per (dir,slice)

// ---------------------------------------------------------------------------
// f32x2 packed-math helpers
// ---------------------------------------------------------------------------
static __device__ __forceinline__ unsigned long long pk2(float x, float y) {
    unsigned long long r;
    asm("mov.b64 %0, {%1, %2};" : "=l"(r) : "f"(x), "f"(y));
    return r;
}
static __device__ __forceinline__ unsigned long long fma2(
    unsigned long long a, unsigned long long b, unsigned long long c) {
    unsigned long long d;
    asm("fma.rn.f32x2 %0, %1, %2, %3;" : "=l"(d) : "l"(a), "l"(b), "l"(c));
    return d;
}
static __device__ __forceinline__ float2 upk(unsigned long long v) {
    float2 r;
    asm("mov.b64 {%0, %1}, %2;" : "=f"(r.x), "=f"(r.y) : "l"(v));
    return r;
}

static __device__ __forceinline__ float sigm_f(float x) {
    return __frcp_rn(1.f + __expf(-x));
}
static __device__ __forceinline__ float tanh_f(float x) {
    x = fminf(fmaxf(x, -15.f), 15.f);
    float e = __expf(2.f * x);
    return (e - 1.f) / (e + 1.f);
}

static __device__ __forceinline__ void st_rel(unsigned* p, unsigned v) {
    asm volatile("st.release.gpu.u32 [%0], %1;" :: "l"(p), "r"(v) : "memory");
}
static __device__ __forceinline__ unsigned ld_acq(const unsigned* p) {
    unsigned v;
    asm volatile("ld.acquire.gpu.u32 %0, [%1];" : "=r"(v) : "l"(p) : "memory");
    return v;
}

// ---------------------------------------------------------------------------
// Reset: zero h state (both phases) and barrier state. Runs every launch.
// ---------------------------------------------------------------------------
__global__ void reset_k() {
    unsigned i = blockIdx.x * 256u + threadIdx.x;
    float* h = &h_glob[0][0][0];
    if (i < 65536u) h[i] = 0.f;
    if (i < 4096u) (&g_arrive[0][0][0])[i] = 0u;
}

// ---------------------------------------------------------------------------
// Phase 1: G[m][j] = x[m,:] . Wih[j,:] + bih[j] + bhh[j]
// 128x128x8 tiles, 256 threads, 8x8 per-thread, f32x2 packed FMA.
// ---------------------------------------------------------------------------
__global__ void __launch_bounds__(256) gemm_in(
    const float* __restrict__ A,
    const float* __restrict__ Wf, const float* __restrict__ Wb,
    const float* __restrict__ bif, const float* __restrict__ bhf,
    const float* __restrict__ bib, const float* __restrict__ bhb)
{
    __shared__ float As[8][132];
    __shared__ float Bs[8][132];

    const int bn = blockIdx.x;          // 0..15
    const int bm = blockIdx.y;          // 0..511
    const bool fwd = (bn < 8);
    const float* Bm = fwd ? Wf : Wb;
    const int nloc = (bn & 7) * 128;

    const int tid = threadIdx.x;
    const int lr  = tid >> 1;
    const int lk  = (tid & 1) * 4;

    const float* Ap = A  + (size_t)(bm * 128 + lr) * 512 + lk;
    const float* Bp = Bm + (size_t)(nloc + lr) * 512 + lk;

    const int tx = tid & 15;
    const int ty = tid >> 4;

    unsigned long long acc[8][4];
#pragma unroll
    for (int i = 0; i < 8; i++)
#pragma unroll
        for (int j = 0; j < 4; j++) acc[i][j] = 0ull;

    float4 pa = *(const float4*)(Ap);
    float4 pb = *(const float4*)(Bp);

    for (int k0 = 0; k0 < 512; k0 += 8) {
        As[lk + 0][lr] = pa.x; As[lk + 1][lr] = pa.y;
        As[lk + 2][lr] = pa.z; As[lk + 3][lr] = pa.w;
        Bs[lk + 0][lr] = pb.x; Bs[lk + 1][lr] = pb.y;
        Bs[lk + 2][lr] = pb.z; Bs[lk + 3][lr] = pb.w;
        __syncthreads();

        if (k0 + 8 < 512) {
            pa = *(const float4*)(Ap + k0 + 8);
            pb = *(const float4*)(Bp + k0 + 8);
        }

#pragma unroll
        for (int kk = 0; kk < 8; kk++) {
            float4 a0 = *(const float4*)&As[kk][ty * 8];
            float4 a1 = *(const float4*)&As[kk][ty * 8 + 4];
            float4 b0 = *(const float4*)&Bs[kk][tx * 8];
            float4 b1 = *(const float4*)&Bs[kk][tx * 8 + 4];
            unsigned long long bb[4] = {
                pk2(b0.x, b0.y), pk2(b0.z, b0.w),
                pk2(b1.x, b1.y), pk2(b1.z, b1.w)
            };
            float av[8] = {a0.x, a0.y, a0.z, a0.w, a1.x, a1.y, a1.z, a1.w};
#pragma unroll
            for (int i = 0; i < 8; i++) {
                unsigned long long aa = pk2(av[i], av[i]);
#pragma unroll
                for (int j = 0; j < 4; j++)
                    acc[i][j] = fma2(aa, bb[j], acc[i][j]);
            }
        }
        __syncthreads();
    }

    const float* bi = fwd ? bif : bib;
    const float* bh = fwd ? bhf : bhb;
    float bias[8];
#pragma unroll
    for (int j = 0; j < 8; j++) {
        int nl = nloc + tx * 8 + j;
        bias[j] = bi[nl] + bh[nl];
    }
#pragma unroll
    for (int i = 0; i < 8; i++) {
        int m = bm * 128 + ty * 8 + i;
        float* dst = G_buf + (size_t)m * 2048 + bn * 128 + tx * 8;
        float2 c0 = upk(acc[i][0]), c1 = upk(acc[i][1]);
        float2 c2 = upk(acc[i][2]), c3 = upk(acc[i][3]);
        *(float4*)dst       = make_float4(c0.x + bias[0], c0.y + bias[1],
                                          c1.x + bias[2], c1.y + bias[3]);
        *(float4*)(dst + 4) = make_float4(c2.x + bias[4], c2.y + bias[5],
                                          c3.x + bias[6], c3.y + bias[7]);
    }
}

// ---------------------------------------------------------------------------
// Transpose G[b*1024+t][j] -> Gt[t][j][b]
// ---------------------------------------------------------------------------
__global__ void __launch_bounds__(256) transp() {
    __shared__ float tile[64][65];
    const int t  = blockIdx.y;
    const int j0 = blockIdx.x * 64;
    const int tid = threadIdx.x;

    const int jq = (tid & 15) * 4;
    const int bb = tid >> 4;
#pragma unroll
    for (int p = 0; p < 4; p++) {
        int bi = bb + p * 16;
        float4 v = *(const float4*)(G_buf + ((size_t)(bi * 1024 + t)) * 2048 + j0 + jq);
        tile[bi][jq + 0] = v.x; tile[bi][jq + 1] = v.y;
        tile[bi][jq + 2] = v.z; tile[bi][jq + 3] = v.w;
    }
    __syncthreads();

    const int bq = (tid & 15) * 4;
    const int jj = tid >> 4;
#pragma unroll
    for (int p = 0; p < 4; p++) {
        int j = jj + p * 16;
        float4 v = make_float4(tile[bq + 0][j], tile[bq + 1][j],
                               tile[bq + 2][j], tile[bq + 3][j]);
        *(float4*)(Gt_buf + ((size_t)t * 2048 + j0 + j) * 64 + bq) = v;
    }
}

// ---------------------------------------------------------------------------
// Phase 2: persistent recurrence. 128 CTAs (64 per direction), 256 threads.
// Warps 0-3 compute: thread (b = tid&63, qp = tid>>6 in {0,1}) owns q-pair
// (qb+2qp, qb+2qp+1) -> per k: 1 h-wavefront + 2 w-broadcast wavefronts for
// 4 fma2 (25% fewer smem wavefronts than 1q/thread). Warps 4-7 only help
// stage the 64KB h exchange, then park at barriers.
// Flat low-contention barrier: padded per-CTA arrive lines polled directly.
// ---------------------------------------------------------------------------
__global__ void __launch_bounds__(256, 1) recur(
    const float* __restrict__ Whf, const float* __restrict__ Whb,
    float* __restrict__ out)
{
    extern __shared__ float sm[];
    float* h_s = sm;                                     // [256][64] = 16384 f (64KB)
    ulonglong2* w_s = (ulonglong2*)(sm + 16384);         // [2][256][2] = 16KB

    const int cta   = blockIdx.x;
    const int dir   = cta >> 6;
    const int slice = cta & 63;
    const int qb    = slice * 4;
    const int tid   = threadIdx.x;
    const int b     = tid & 63;
    const int qp    = (tid >> 6) & 1;
    const bool comp = (tid < 128);
    const int q0    = qb + qp * 2;      // this thread's q pair: q0, q0+1

    // Fill w_s: entry (qp,k) = { (wi,wf),(wg,wo) for q0 ; same for q0+1 } (32B)
    const float* W = dir ? Whb : Whf;
    for (int idx = tid; idx < 512; idx += 256) {
        int eqp = idx >> 8;
        int k   = idx & 255;
        int qa  = qb + eqp * 2;
#pragma unroll
        for (int j = 0; j < 2; j++) {
            int qg = qa + j;
            ulonglong2 v;
            v.x = pk2(W[(size_t)(      qg) * 256 + k], W[(size_t)(256 + qg) * 256 + k]);
            v.y = pk2(W[(size_t)(512 + qg) * 256 + k], W[(size_t)(768 + qg) * 256 + k]);
            w_s[(eqp * 256 + k) * 2 + j] = v;
        }
    }

    const ulonglong2* wrow = w_s + qp * 512;
    float c0 = 0.f, c1 = 0.f;

    // Prefetch gate pre-activations for step 0 (compute threads only)
    int t = dir ? 1023 : 0;
    float pi0, pf0, pg0, po0, pi1, pf1, pg1, po1;
    {
        const float* gp = Gt_buf + ((size_t)t * 2048 + (size_t)dir * 1024) * 64 + b;
        pi0 = __ldg(gp + (size_t)(      q0) * 64);
        pf0 = __ldg(gp + (size_t)(256 + q0) * 64);
        pg0 = __ldg(gp + (size_t)(512 + q0) * 64);
        po0 = __ldg(gp + (size_t)(768 + q0) * 64);
        pi1 = __ldg(gp + (size_t)(      q0 + 1) * 64);
        pf1 = __ldg(gp + (size_t)(256 + q0 + 1) * 64);
        pg1 = __ldg(gp + (size_t)(512 + q0 + 1) * 64);
        po1 = __ldg(gp + (size_t)(768 + q0 + 1) * 64);
    }

    for (int step = 0; step < 1024; ++step) {
        // Stage h (64KB): all 8 warps, 16 float4 each, batched L2 loads.
        {
            const float4* src = (const float4*)(&h_glob[step & 1][dir][0]);
            float4* dst = (float4*)h_s;
            float4 v[16];
#pragma unroll
            for (int i = 0; i < 16; i++)
                v[i] = __ldcg(src + tid + i * 256);
#pragma unroll
            for (int i = 0; i < 16; i++)
                dst[tid + i * 256] = v[i];
        }
        __syncthreads();   // also covers w_s on the first iteration

        float hn0, hn1;
        if (comp) {
            unsigned long long aif0 = pk2(pi0, pf0);
            unsigned long long ago0 = pk2(pg0, po0);
            unsigned long long aif1 = pk2(pi1, pf1);
            unsigned long long ago1 = pk2(pg1, po1);

#pragma unroll 8
            for (int k = 0; k < 256; ++k) {
                float hv = h_s[k * 64 + b];
                unsigned long long hh = pk2(hv, hv);
                ulonglong2 wA = wrow[k * 2 + 0];
                ulonglong2 wB = wrow[k * 2 + 1];
                aif0 = fma2(hh, wA.x, aif0);
                ago0 = fma2(hh, wA.y, ago0);
                aif1 = fma2(hh, wB.x, aif1);
                ago1 = fma2(hh, wB.y, ago1);
            }

            float2 vif0 = upk(aif0), vgo0 = upk(ago0);
            float2 vif1 = upk(aif1), vgo1 = upk(ago1);
            float ig0 = sigm_f(vif0.x), fg0 = sigm_f(vif0.y);
            float gg0 = tanh_f(vgo0.x), og0 = sigm_f(vgo0.y);
            float ig1 = sigm_f(vif1.x), fg1 = sigm_f(vif1.y);
            float gg1 = tanh_f(vgo1.x), og1 = sigm_f(vgo1.y);
            c0 = fg0 * c0 + ig0 * gg0;
            c1 = fg1 * c1 + ig1 * gg1;
            hn0 = og0 * tanh_f(c0);
            hn1 = og1 * tanh_f(c1);

            __stcg(&h_glob[(step + 1) & 1][dir][(q0    ) * 64 + b], hn0);
            __stcg(&h_glob[(step + 1) & 1][dir][(q0 + 1) * 64 + b], hn1);
        }

        if (step == 1023) {
            if (comp) {
                out[((size_t)b * 1024 + t) * 512 + (size_t)dir * 256 + q0    ] = hn0;
                out[((size_t)b * 1024 + t) * 512 + (size_t)dir * 256 + q0 + 1] = hn1;
            }
            break;
        }

        // ---- arrive: push h stores, signal this CTA's padded flag ----
        __threadfence();
        __syncthreads();
        if (tid == 0) st_rel(&g_arrive[dir][slice][0], (unsigned)(step + 1));

        // Hidden under the wait: output stores + next step's gate prefetch
        if (comp) {
            out[((size_t)b * 1024 + t) * 512 + (size_t)dir * 256 + q0    ] = hn0;
            out[((size_t)b * 1024 + t) * 512 + (size_t)dir * 256 + q0 + 1] = hn1;
            int tn = dir ? (1022 - step) : (step + 1);
            const float* gp = Gt_buf + ((size_t)tn * 2048 + (size_t)dir * 1024) * 64 + b;
            pi0 = __ldg(gp + (size_t)(      q0) * 64);
            pf0 = __ldg(gp + (size_t)(256 + q0) * 64);
            pg0 = __ldg(gp + (size_t)(512 + q0) * 64);
            po0 = __ldg(gp + (size_t)(768 + q0) * 64);
            pi1 = __ldg(gp + (size_t)(      q0 + 1) * 64);
            pf1 = __ldg(gp + (size_t)(256 + q0 + 1) * 64);
            pg1 = __ldg(gp + (size_t)(512 + q0 + 1) * 64);
            po1 = __ldg(gp + (size_t)(768 + q0 + 1) * 64);
        }
        t = dir ? (1022 - step) : (step + 1);

        // ---- wait: poll all 64 padded arrive lines directly (64 pollers/line)
        if (tid < 64) {
            while (ld_acq(&g_arrive[dir][tid][0]) <= (unsigned)step) {}
        }
        __syncthreads();
    }
}

// ---------------------------------------------------------------------------
// Launch
// ---------------------------------------------------------------------------
extern "C" void kernel_launch(void* const* d_in, const int* in_sizes, int n_in,
                              void* d_out, int out_size) {
    const float* x   = (const float*)d_in[0];
    const float* Wif = (const float*)d_in[1];
    const float* Whf = (const float*)d_in[2];
    const float* bif = (const float*)d_in[3];
    const float* bhf = (const float*)d_in[4];
    const float* Wib = (const float*)d_in[5];
    const float* Whb = (const float*)d_in[6];
    const float* bib = (const float*)d_in[7];
    const float* bhb = (const float*)d_in[8];
    float* out = (float*)d_out;

    cudaFuncSetAttribute(recur, cudaFuncAttributeMaxDynamicSharedMemorySize, 81920);

    reset_k<<<256, 256>>>();
    gemm_in<<<dim3(16, 512), 256>>>(x, Wif, Wib, bif, bhf, bib, bhb);
    transp<<<dim3(32, 1024), 256>>>();
    recur<<<128, 256, 81920>>>(Whf, Whb, out);
}

// round 7
// speedup vs baseline: 2.0763x; 1.0671x over previous
#include <cuda_runtime.h>
#include <cuda_bf16.h>

// Sizes (fixed): B=64, T=1024, D=512, H=256, 4H=1024, two directions.

// ---------------------------------------------------------------------------
// Scratch (device globals -- no allocation allowed)
// ---------------------------------------------------------------------------
__device__ float G_buf [(size_t)65536 * 2048];        // [m = b*1024 + t][j(0..2047)]
__device__ float Gt_buf[(size_t)1024 * 2048 * 64];    // [t][j][b]
__device__ float Hhist [(size_t)2 * 1024 * 16384];    // [dir][t][q*64 + b]
__device__ unsigned g_arrive[2][64][32];              // padded: one 128B line per (dir,slice)

// ---------------------------------------------------------------------------
// f32x2 packed-math helpers
// ---------------------------------------------------------------------------
static __device__ __forceinline__ unsigned long long pk2(float x, float y) {
    unsigned long long r;
    asm("mov.b64 %0, {%1, %2};" : "=l"(r) : "f"(x), "f"(y));
    return r;
}
static __device__ __forceinline__ unsigned long long fma2(
    unsigned long long a, unsigned long long b, unsigned long long c) {
    unsigned long long d;
    asm("fma.rn.f32x2 %0, %1, %2, %3;" : "=l"(d) : "l"(a), "l"(b), "l"(c));
    return d;
}
static __device__ __forceinline__ unsigned long long add2(
    unsigned long long a, unsigned long long b) {
    unsigned long long d;
    asm("add.rn.f32x2 %0, %1, %2;" : "=l"(d) : "l"(a), "l"(b));
    return d;
}
static __device__ __forceinline__ float2 upk(unsigned long long v) {
    float2 r;
    asm("mov.b64 {%0, %1}, %2;" : "=f"(r.x), "=f"(r.y) : "l"(v));
    return r;
}

static __device__ __forceinline__ float sigm_f(float x) {
    return __frcp_rn(1.f + __expf(-x));
}
static __device__ __forceinline__ float tanh_f(float x) {
    x = fminf(fmaxf(x, -15.f), 15.f);
    float e = __expf(2.f * x);
    return (e - 1.f) / (e + 1.f);
}

static __device__ __forceinline__ void st_rel(unsigned* p, unsigned v) {
    asm volatile("st.release.gpu.u32 [%0], %1;" :: "l"(p), "r"(v) : "memory");
}
static __device__ __forceinline__ unsigned ld_acq(const unsigned* p) {
    unsigned v;
    asm volatile("ld.acquire.gpu.u32 %0, [%1];" : "=r"(v) : "l"(p) : "memory");
    return v;
}

// ---------------------------------------------------------------------------
// Reset: zero barrier state. Runs every launch.
// ---------------------------------------------------------------------------
__global__ void reset_k() {
    unsigned i = blockIdx.x * 256u + threadIdx.x;
    if (i < 4096u) (&g_arrive[0][0][0])[i] = 0u;
}

// ---------------------------------------------------------------------------
// Phase 1: G[m][j] = x[m,:] . Wih[j,:] + bih[j] + bhh[j]
// 128x128x8 tiles, 256 threads, 8x8 per-thread, f32x2 packed FMA.
// ---------------------------------------------------------------------------
__global__ void __launch_bounds__(256) gemm_in(
    const float* __restrict__ A,
    const float* __restrict__ Wf, const float* __restrict__ Wb,
    const float* __restrict__ bif, const float* __restrict__ bhf,
    const float* __restrict__ bib, const float* __restrict__ bhb)
{
    __shared__ float As[8][132];
    __shared__ float Bs[8][132];

    const int bn = blockIdx.x;          // 0..15
    const int bm = blockIdx.y;          // 0..511
    const bool fwd = (bn < 8);
    const float* Bm = fwd ? Wf : Wb;
    const int nloc = (bn & 7) * 128;

    const int tid = threadIdx.x;
    const int lr  = tid >> 1;
    const int lk  = (tid & 1) * 4;

    const float* Ap = A  + (size_t)(bm * 128 + lr) * 512 + lk;
    const float* Bp = Bm + (size_t)(nloc + lr) * 512 + lk;

    const int tx = tid & 15;
    const int ty = tid >> 4;

    unsigned long long acc[8][4];
#pragma unroll
    for (int i = 0; i < 8; i++)
#pragma unroll
        for (int j = 0; j < 4; j++) acc[i][j] = 0ull;

    float4 pa = *(const float4*)(Ap);
    float4 pb = *(const float4*)(Bp);

    for (int k0 = 0; k0 < 512; k0 += 8) {
        As[lk + 0][lr] = pa.x; As[lk + 1][lr] = pa.y;
        As[lk + 2][lr] = pa.z; As[lk + 3][lr] = pa.w;
        Bs[lk + 0][lr] = pb.x; Bs[lk + 1][lr] = pb.y;
        Bs[lk + 2][lr] = pb.z; Bs[lk + 3][lr] = pb.w;
        __syncthreads();

        if (k0 + 8 < 512) {
            pa = *(const float4*)(Ap + k0 + 8);
            pb = *(const float4*)(Bp + k0 + 8);
        }

#pragma unroll
        for (int kk = 0; kk < 8; kk++) {
            float4 a0 = *(const float4*)&As[kk][ty * 8];
            float4 a1 = *(const float4*)&As[kk][ty * 8 + 4];
            float4 b0 = *(const float4*)&Bs[kk][tx * 8];
            float4 b1 = *(const float4*)&Bs[kk][tx * 8 + 4];
            unsigned long long bb[4] = {
                pk2(b0.x, b0.y), pk2(b0.z, b0.w),
                pk2(b1.x, b1.y), pk2(b1.z, b1.w)
            };
            float av[8] = {a0.x, a0.y, a0.z, a0.w, a1.x, a1.y, a1.z, a1.w};
#pragma unroll
            for (int i = 0; i < 8; i++) {
                unsigned long long aa = pk2(av[i], av[i]);
#pragma unroll
                for (int j = 0; j < 4; j++)
                    acc[i][j] = fma2(aa, bb[j], acc[i][j]);
            }
        }
        __syncthreads();
    }

    const float* bi = fwd ? bif : bib;
    const float* bh = fwd ? bhf : bhb;
    float bias[8];
#pragma unroll
    for (int j = 0; j < 8; j++) {
        int nl = nloc + tx * 8 + j;
        bias[j] = bi[nl] + bh[nl];
    }
#pragma unroll
    for (int i = 0; i < 8; i++) {
        int m = bm * 128 + ty * 8 + i;
        float* dst = G_buf + (size_t)m * 2048 + bn * 128 + tx * 8;
        float2 c0 = upk(acc[i][0]), c1 = upk(acc[i][1]);
        float2 c2 = upk(acc[i][2]), c3 = upk(acc[i][3]);
        *(float4*)dst       = make_float4(c0.x + bias[0], c0.y + bias[1],
                                          c1.x + bias[2], c1.y + bias[3]);
        *(float4*)(dst + 4) = make_float4(c2.x + bias[4], c2.y + bias[5],
                                          c3.x + bias[6], c3.y + bias[7]);
    }
}

// ---------------------------------------------------------------------------
// Transpose G[b*1024+t][j] -> Gt[t][j][b]
// ---------------------------------------------------------------------------
__global__ void __launch_bounds__(256) transp() {
    __shared__ float tile[64][65];
    const int t  = blockIdx.y;
    const int j0 = blockIdx.x * 64;
    const int tid = threadIdx.x;

    const int jq = (tid & 15) * 4;
    const int bb = tid >> 4;
#pragma unroll
    for (int p = 0; p < 4; p++) {
        int bi = bb + p * 16;
        float4 v = *(const float4*)(G_buf + ((size_t)(bi * 1024 + t)) * 2048 + j0 + jq);
        tile[bi][jq + 0] = v.x; tile[bi][jq + 1] = v.y;
        tile[bi][jq + 2] = v.z; tile[bi][jq + 3] = v.w;
    }
    __syncthreads();

    const int bq = (tid & 15) * 4;
    const int jj = tid >> 4;
#pragma unroll
    for (int p = 0; p < 4; p++) {
        int j = jj + p * 16;
        float4 v = make_float4(tile[bq + 0][j], tile[bq + 1][j],
                               tile[bq + 2][j], tile[bq + 3][j]);
        *(float4*)(Gt_buf + ((size_t)t * 2048 + j0 + j) * 64 + bq) = v;
    }
}

// ---------------------------------------------------------------------------
// Phase 2: persistent recurrence. 128 CTAs (64 per direction), 256 threads.
// Thread = (b = tid&63, qp = (tid>>6)&1, kh = tid>>7). All 8 warps compute:
// kh splits the k-dimension in half (2 warps per SMSP hide LDS latency),
// partials combined through smem. h history stored coalesced to Hhist, which
// is also the cross-CTA h exchange (no ping-pong buffer, no scattered out[]).
// Flat low-contention barrier: padded per-CTA arrive lines polled directly.
// ---------------------------------------------------------------------------
__global__ void __launch_bounds__(256, 1) recur(
    const float* __restrict__ Whf, const float* __restrict__ Whb)
{
    extern __shared__ float sm[];
    float* h_s = sm;                                     // [256][64] 64KB
    ulonglong2* w_s = (ulonglong2*)(sm + 16384);         // [2][256][2] 16KB
    unsigned long long* red = (unsigned long long*)(sm + 16384 + 4096); // [128][4] 4KB

    const int cta   = blockIdx.x;
    const int dir   = cta >> 6;
    const int slice = cta & 63;
    const int qb    = slice * 4;
    const int tid   = threadIdx.x;
    const int b     = tid & 63;
    const int qp    = (tid >> 6) & 1;
    const int kh    = tid >> 7;          // 0: k in [0,128), 1: k in [128,256)
    const bool lo   = (tid < 128);
    const int q0    = qb + qp * 2;       // this thread's q pair: q0, q0+1

    // Fill w_s: entry (qp,k,j) = (wi,wf),(wg,wo) for q = qb+2qp+j
    const float* W = dir ? Whb : Whf;
    for (int idx = tid; idx < 512; idx += 256) {
        int eqp = idx >> 8;
        int k   = idx & 255;
        int qa  = qb + eqp * 2;
#pragma unroll
        for (int j = 0; j < 2; j++) {
            int qg = qa + j;
            ulonglong2 v;
            v.x = pk2(W[(size_t)(      qg) * 256 + k], W[(size_t)(256 + qg) * 256 + k]);
            v.y = pk2(W[(size_t)(512 + qg) * 256 + k], W[(size_t)(768 + qg) * 256 + k]);
            w_s[(eqp * 256 + k) * 2 + j] = v;
        }
    }

    const ulonglong2* wrow = w_s + (qp * 256 + kh * 128) * 2;
    const float*      hrow = h_s + kh * 128 * 64 + b;
    float c0 = 0.f, c1 = 0.f;

    // Prefetch gate pre-activations for step 0 (lo threads finalize gates)
    int t = dir ? 1023 : 0;
    float pi0, pf0, pg0, po0, pi1, pf1, pg1, po1;
    if (lo) {
        const float* gp = Gt_buf + ((size_t)t * 2048 + (size_t)dir * 1024) * 64 + b;
        pi0 = __ldg(gp + (size_t)(      q0) * 64);
        pf0 = __ldg(gp + (size_t)(256 + q0) * 64);
        pg0 = __ldg(gp + (size_t)(512 + q0) * 64);
        po0 = __ldg(gp + (size_t)(768 + q0) * 64);
        pi1 = __ldg(gp + (size_t)(      q0 + 1) * 64);
        pf1 = __ldg(gp + (size_t)(256 + q0 + 1) * 64);
        pg1 = __ldg(gp + (size_t)(512 + q0 + 1) * 64);
        po1 = __ldg(gp + (size_t)(768 + q0 + 1) * 64);
    }

    float* Hd = Hhist + (size_t)dir * 1024 * 16384;

    for (int step = 0; step < 1024; ++step) {
        // Stage h (64KB): step 0 -> zeros; else read previous t's row of Hhist.
        if (step == 0) {
            float4 z = make_float4(0.f, 0.f, 0.f, 0.f);
            float4* dst = (float4*)h_s;
#pragma unroll
            for (int i = 0; i < 16; i++)
                dst[tid + i * 256] = z;
        } else {
            const int tp = dir ? (t + 1) : (t - 1);
            const float4* src = (const float4*)(Hd + (size_t)tp * 16384);
            float4* dst = (float4*)h_s;
            float4 v[16];
#pragma unroll
            for (int i = 0; i < 16; i++)
                v[i] = __ldcg(src + tid + i * 256);
#pragma unroll
            for (int i = 0; i < 16; i++)
                dst[tid + i * 256] = v[i];
        }
        __syncthreads();   // also covers w_s on the first iteration

        unsigned long long aif0, ago0, aif1, ago1;
        if (lo) {
            aif0 = pk2(pi0, pf0); ago0 = pk2(pg0, po0);
            aif1 = pk2(pi1, pf1); ago1 = pk2(pg1, po1);
        } else {
            aif0 = ago0 = aif1 = ago1 = 0ull;
        }

#pragma unroll 8
        for (int k = 0; k < 128; ++k) {
            float hv = hrow[k * 64];
            unsigned long long hh = pk2(hv, hv);
            ulonglong2 wA = wrow[k * 2 + 0];
            ulonglong2 wB = wrow[k * 2 + 1];
            aif0 = fma2(hh, wA.x, aif0);
            ago0 = fma2(hh, wA.y, ago0);
            aif1 = fma2(hh, wB.x, aif1);
            ago1 = fma2(hh, wB.y, ago1);
        }

        // Cross-half reduction: hi threads publish partials, lo threads combine.
        if (!lo) {
            unsigned long long* r = red + (size_t)(tid - 128) * 4;
            r[0] = aif0; r[1] = ago0; r[2] = aif1; r[3] = ago1;
        }
        __syncthreads();

        float hn0, hn1;
        if (lo) {
            const unsigned long long* r = red + (size_t)tid * 4;
            aif0 = add2(aif0, r[0]);
            ago0 = add2(ago0, r[1]);
            aif1 = add2(aif1, r[2]);
            ago1 = add2(ago1, r[3]);

            float2 vif0 = upk(aif0), vgo0 = upk(ago0);
            float2 vif1 = upk(aif1), vgo1 = upk(ago1);
            float ig0 = sigm_f(vif0.x), fg0 = sigm_f(vif0.y);
            float gg0 = tanh_f(vgo0.x), og0 = sigm_f(vgo0.y);
            float ig1 = sigm_f(vif1.x), fg1 = sigm_f(vif1.y);
            float gg1 = tanh_f(vgo1.x), og1 = sigm_f(vgo1.y);
            c0 = fg0 * c0 + ig0 * gg0;
            c1 = fg1 * c1 + ig1 * gg1;
            hn0 = og0 * tanh_f(c0);
            hn1 = og1 * tanh_f(c1);

            float* hd = Hd + (size_t)t * 16384;
            __stcg(hd + (q0    ) * 64 + b, hn0);
            __stcg(hd + (q0 + 1) * 64 + b, hn1);
        }

        if (step == 1023) break;

        // ---- arrive: push Hhist stores, signal this CTA's padded flag ----
        __threadfence();
        __syncthreads();
        if (tid == 0) st_rel(&g_arrive[dir][slice][0], (unsigned)(step + 1));

        // Hidden under the wait: next step's gate prefetch
        t = dir ? (1022 - step) : (step + 1);
        if (lo) {
            const float* gp = Gt_buf + ((size_t)t * 2048 + (size_t)dir * 1024) * 64 + b;
            pi0 = __ldg(gp + (size_t)(      q0) * 64);
            pf0 = __ldg(gp + (size_t)(256 + q0) * 64);
            pg0 = __ldg(gp + (size_t)(512 + q0) * 64);
            po0 = __ldg(gp + (size_t)(768 + q0) * 64);
            pi1 = __ldg(gp + (size_t)(      q0 + 1) * 64);
            pf1 = __ldg(gp + (size_t)(256 + q0 + 1) * 64);
            pg1 = __ldg(gp + (size_t)(512 + q0 + 1) * 64);
            po1 = __ldg(gp + (size_t)(768 + q0 + 1) * 64);
        }

        // ---- wait: poll all 64 padded arrive lines (64 pollers per line) ----
        if (tid < 64) {
            while (ld_acq(&g_arrive[dir][tid][0]) <= (unsigned)step) {}
        }
        __syncthreads();
    }
}

// ---------------------------------------------------------------------------
// Final: out[b][t][dir*256+q] = Hhist[dir][t][q*64+b]
// grid (4 qblk, 1024 t, 2 dir), 256 threads, 64q x 64b smem tile.
// ---------------------------------------------------------------------------
__global__ void __launch_bounds__(256) out_tr(float* __restrict__ out) {
    __shared__ float tile[64][65];   // [b][qq]
    const int q0  = blockIdx.x * 64;
    const int t   = blockIdx.y;
    const int dir = blockIdx.z;
    const int tid = threadIdx.x;

    const float* src = Hhist + ((size_t)dir * 1024 + t) * 16384;
    const int b  = tid & 63;
    const int q4 = (tid >> 6) * 16;
#pragma unroll
    for (int i = 0; i < 16; i++) {
        int qq = q4 + i;
        tile[b][qq] = src[(q0 + qq) * 64 + b];
    }
    __syncthreads();

    const int qs = (tid & 15) * 4;
    const int br = tid >> 4;
#pragma unroll
    for (int p = 0; p < 4; p++) {
        int bb = br + p * 16;
        float4 v = make_float4(tile[bb][qs + 0], tile[bb][qs + 1],
                               tile[bb][qs + 2], tile[bb][qs + 3]);
        *(float4*)(out + ((size_t)bb * 1024 + t) * 512 + dir * 256 + q0 + qs) = v;
    }
}

// ---------------------------------------------------------------------------
// Launch
// ---------------------------------------------------------------------------
extern "C" void kernel_launch(void* const* d_in, const int* in_sizes, int n_in,
                              void* d_out, int out_size) {
    const float* x   = (const float*)d_in[0];
    const float* Wif = (const float*)d_in[1];
    const float* Whf = (const float*)d_in[2];
    const float* bif = (const float*)d_in[3];
    const float* bhf = (const float*)d_in[4];
    const float* Wib = (const float*)d_in[5];
    const float* Whb = (const float*)d_in[6];
    const float* bib = (const float*)d_in[7];
    const float* bhb = (const float*)d_in[8];
    float* out = (float*)d_out;

    cudaFuncSetAttribute(recur, cudaFuncAttributeMaxDynamicSharedMemorySize, 90112);

    reset_k<<<16, 256>>>();
    gemm_in<<<dim3(16, 512), 256>>>(x, Wif, Wib, bif, bhf, bib, bhb);
    transp<<<dim3(32, 1024), 256>>>();
    recur<<<128, 256, 90112>>>(Whf, Whb);
    out_tr<<<dim3(4, 1024, 2), 256>>>(out);
}